// round 1
// baseline (speedup 1.0000x reference)
#include <cuda_runtime.h>
#include <cuda_bf16.h>

#define BIG 1e4f
#define IMH 1024
#define IMW 1024

constexpr int TX = 128;              // output tile width (floats)
constexpr int TY = 32;               // output tile height
constexpr int NTHREADS = 256;
constexpr int IN_ROWS = TY + 4;      // 36 input rows (halo 2 each side)
constexpr int IN_C4   = TX / 4 + 2;  // 34 float4 per row (halo 4 floats each side)
constexpr int ER_ROWS = TY + 2;      // 34 eroded rows (halo 1 each side)

__device__ __forceinline__ float4 f4min(float4 a, float4 b) {
    return make_float4(fminf(a.x,b.x), fminf(a.y,b.y), fminf(a.z,b.z), fminf(a.w,b.w));
}
__device__ __forceinline__ float4 f4max(float4 a, float4 b) {
    return make_float4(fmaxf(a.x,b.x), fmaxf(a.y,b.y), fmaxf(a.z,b.z), fmaxf(a.w,b.w));
}
// window shifted by dx=-1: value at lane k is element (k-1)
__device__ __forceinline__ float4 shl(float L, float4 v) {
    return make_float4(L, v.x, v.y, v.z);
}
// window shifted by dx=+1: value at lane k is element (k+1)
__device__ __forceinline__ float4 shr(float4 v, float R) {
    return make_float4(v.y, v.z, v.w, R);
}

__global__ __launch_bounds__(NTHREADS)
void opening_kernel(const float* __restrict__ img,
                    const int*   __restrict__ ker,
                    float*       __restrict__ out)
{
    __shared__ float4 sin_t[IN_ROWS][IN_C4];   // input tile, +BIG outside image
    __shared__ float4 ser_t[ER_ROWS][IN_C4];   // eroded tile, -BIG outside image

    const int bc  = blockIdx.z;                 // fused batch*channel
    const int gx0 = blockIdx.x * TX;
    const int gy0 = blockIdx.y * TY;
    const int tid = threadIdx.x;

    const float* __restrict__ src = img + (size_t)bc * IMH * IMW;
    float*       __restrict__ dst = out + (size_t)bc * IMH * IMW;

    // structuring-element mask (uniform across block)
    int km[9];
    #pragma unroll
    for (int i = 0; i < 9; i++) km[i] = ker[i];

    // ---- Phase 1: load input tile with halo; out-of-image -> +BIG ----
    for (int idx = tid; idx < IN_ROWS * IN_C4; idx += NTHREADS) {
        int r  = idx / IN_C4;
        int c4 = idx % IN_C4;
        int gy  = gy0 - 2 + r;
        int gxs = gx0 - 4 + c4 * 4;   // 16B-aligned
        float4 v;
        if (gy < 0 || gy >= IMH) {
            v = make_float4(BIG, BIG, BIG, BIG);
        } else if (gxs >= 0 && gxs + 3 < IMW) {
            v = *reinterpret_cast<const float4*>(src + (size_t)gy * IMW + gxs);
        } else {
            float t0 = (gxs+0 >= 0 && gxs+0 < IMW) ? src[(size_t)gy*IMW + gxs+0] : BIG;
            float t1 = (gxs+1 >= 0 && gxs+1 < IMW) ? src[(size_t)gy*IMW + gxs+1] : BIG;
            float t2 = (gxs+2 >= 0 && gxs+2 < IMW) ? src[(size_t)gy*IMW + gxs+2] : BIG;
            float t3 = (gxs+3 >= 0 && gxs+3 < IMW) ? src[(size_t)gy*IMW + gxs+3] : BIG;
            v = make_float4(t0, t1, t2, t3);
        }
        sin_t[r][c4] = v;
    }
    __syncthreads();

    // ---- Phase 2: erosion into ser_t (y_local = r-1 in [-1..TY]) ----
    for (int idx = tid; idx < ER_ROWS * IN_C4; idx += NTHREADS) {
        int r  = idx / IN_C4;
        int c4 = idx % IN_C4;
        // input rows: up = r (y-1), mid = r+1 (y), dn = r+2 (y+1)
        float4 rowv[3];
        float  L[3], R[3];
        #pragma unroll
        for (int i = 0; i < 3; i++) {
            rowv[i] = sin_t[r + i][c4];
            L[i] = (c4 > 0)         ? sin_t[r + i][c4 - 1].w : BIG;
            R[i] = (c4 < IN_C4 - 1) ? sin_t[r + i][c4 + 1].x : BIG;
        }
        float4 e = make_float4(BIG, BIG, BIG, BIG);
        #pragma unroll
        for (int i = 0; i < 3; i++) {
            if (km[i*3 + 0]) e = f4min(e, shl(L[i], rowv[i]));
            if (km[i*3 + 1]) e = f4min(e, rowv[i]);
            if (km[i*3 + 2]) e = f4min(e, shr(rowv[i], R[i]));
        }
        // positions outside the image become -BIG (dilation identity)
        int gy  = gy0 + (r - 1);
        int gxs = gx0 - 4 + c4 * 4;
        if (gy < 0 || gy >= IMH) {
            e = make_float4(-BIG, -BIG, -BIG, -BIG);
        } else {
            if (gxs+0 < 0 || gxs+0 >= IMW) e.x = -BIG;
            if (gxs+1 < 0 || gxs+1 >= IMW) e.y = -BIG;
            if (gxs+2 < 0 || gxs+2 >= IMW) e.z = -BIG;
            if (gxs+3 < 0 || gxs+3 >= IMW) e.w = -BIG;
        }
        ser_t[r][c4] = e;
    }
    __syncthreads();

    // ---- Phase 3: dilation of eroded tile + store ----
    const int tx  = tid & 31;        // 32 column groups of 4 floats
    const int tyb = tid >> 5;        // 8 row slots
    const int c4  = tx + 1;          // center float4 (x_local = 4*tx)
    #pragma unroll
    for (int rr = 0; rr < TY; rr += 8) {
        int yl = tyb + rr;           // 0..31
        int r  = yl + 1;             // eroded-row index of center
        float4 rowv[3];
        float  L[3], R[3];
        #pragma unroll
        for (int i = 0; i < 3; i++) {
            rowv[i] = ser_t[r - 1 + i][c4];
            L[i] = ser_t[r - 1 + i][c4 - 1].w;
            R[i] = ser_t[r - 1 + i][c4 + 1].x;
        }
        float4 d = make_float4(-BIG, -BIG, -BIG, -BIG);
        #pragma unroll
        for (int i = 0; i < 3; i++) {
            if (km[i*3 + 0]) d = f4max(d, shl(L[i], rowv[i]));
            if (km[i*3 + 1]) d = f4max(d, rowv[i]);
            if (km[i*3 + 2]) d = f4max(d, shr(rowv[i], R[i]));
        }
        int gy = gy0 + yl;
        int gx = gx0 + 4 * tx;
        *reinterpret_cast<float4*>(dst + (size_t)gy * IMW + gx) = d;
    }
}

extern "C" void kernel_launch(void* const* d_in, const int* in_sizes, int n_in,
                              void* d_out, int out_size)
{
    const float* img = (const float*)d_in[0];   // [8,3,1024,1024] fp32
    const int*   ker = (const int*)d_in[1];     // [3,3] int32 mask
    float*       out = (float*)d_out;

    const int BC = in_sizes[0] / (IMH * IMW);   // 24
    dim3 grid(IMW / TX, IMH / TY, BC);          // (8, 32, 24)
    opening_kernel<<<grid, NTHREADS>>>(img, ker, out);
}

// round 3
// speedup vs baseline: 1.4090x; 1.4090x over previous
#include <cuda_runtime.h>
#include <cuda_bf16.h>

#define BIG 1e4f
#define IMH 1024
#define IMW 1024

constexpr int TY     = 32;   // output rows per warp
constexpr int NSEG   = 8;    // 1024 / 128 horizontal warp segments
constexpr int NSTRIP = IMH / TY;          // 32
constexpr int NTHREADS = 256;             // 8 warps / block

template<bool CROSS>
__device__ __forceinline__ void run_warp(const float* __restrict__ src,
                                         float*       __restrict__ dst,
                                         const int* km, int x0, int y0)
{
    float eA[6], eB[6];   // erosion accumulators: rows q-1, q
    float dA[4], dB[4];   // dilation accumulators: rows q-2, q-1
#pragma unroll
    for (int k = 0; k < 6; k++) { eA[k] = BIG; eB[k] = BIG; }
#pragma unroll
    for (int k = 0; k < 4; k++) { dA[k] = -BIG; dB[k] = -BIG; }

    const bool xlo = (x0 == 0);          // eroded pos x0-1 == -1
    const bool xhi = (x0 == IMW - 4);    // eroded pos x0+4 == IMW

#pragma unroll 4
    for (int q = y0 - 2; q <= y0 + TY + 1; q++) {
        // ---- load 8-wide input window for row q (pad = +BIG) ----
        float w[8];
        if (q >= 0 && q < IMH) {
            const float* p = src + q * IMW + x0;
            float4 v = *reinterpret_cast<const float4*>(p);
            float2 lv = (x0 >= 2)       ? *reinterpret_cast<const float2*>(p - 2)
                                        : make_float2(BIG, BIG);
            float2 rv = (x0 <= IMW - 8) ? *reinterpret_cast<const float2*>(p + 4)
                                        : make_float2(BIG, BIG);
            w[0]=lv.x; w[1]=lv.y; w[2]=v.x; w[3]=v.y; w[4]=v.z; w[5]=v.w; w[6]=rv.x; w[7]=rv.y;
        } else {
#pragma unroll
            for (int k = 0; k < 8; k++) w[k] = BIG;
        }

        // ---- erosion contributions of input row q (6-wide: x0-1..x0+4) ----
        // mask row i applied to input row q contributes to eroded row q+1-i
        float eC[6];
        if (CROSS) {
#pragma unroll
            for (int k = 0; k < 6; k++) {
                float h = fminf(fminf(w[k], w[k + 1]), w[k + 2]);
                eC[k] = w[k + 1];            // mask row 0 = center only
                eB[k] = fminf(eB[k], h);     // mask row 1 = full
                eA[k] = fminf(eA[k], w[k + 1]); // mask row 2 = center only
            }
        } else {
            float c0[6], c1[6], c2[6];
#pragma unroll
            for (int k = 0; k < 6; k++) { c0[k] = BIG; c1[k] = BIG; c2[k] = BIG; }
#pragma unroll
            for (int j = 0; j < 3; j++) {
                if (km[0 * 3 + j]) {
#pragma unroll
                    for (int k = 0; k < 6; k++) c0[k] = fminf(c0[k], w[k + j]);
                }
                if (km[1 * 3 + j]) {
#pragma unroll
                    for (int k = 0; k < 6; k++) c1[k] = fminf(c1[k], w[k + j]);
                }
                if (km[2 * 3 + j]) {
#pragma unroll
                    for (int k = 0; k < 6; k++) c2[k] = fminf(c2[k], w[k + j]);
                }
            }
#pragma unroll
            for (int k = 0; k < 6; k++) {
                eC[k] = c0[k];
                eB[k] = fminf(eB[k], c1[k]);
                eA[k] = fminf(eA[k], c2[k]);
            }
        }

        // ---- eA now complete: eroded row ry = q-1. Apply -BIG padding. ----
        int ry = q - 1;
        if (ry < 0 || ry >= IMH) {
#pragma unroll
            for (int k = 0; k < 6; k++) eA[k] = -BIG;
        } else {
            if (xlo) eA[0] = -BIG;
            if (xhi) eA[5] = -BIG;
        }

        // ---- dilation contributions of eroded row ry (4-wide: x0..x0+3) ----
        float dC[4];
        if (CROSS) {
#pragma unroll
            for (int k = 0; k < 4; k++) {
                float g = fmaxf(fmaxf(eA[k], eA[k + 1]), eA[k + 2]);
                dC[k] = eA[k + 1];
                dB[k] = fmaxf(dB[k], g);
                dA[k] = fmaxf(dA[k], eA[k + 1]);
            }
        } else {
            float g0[4], g1[4], g2[4];
#pragma unroll
            for (int k = 0; k < 4; k++) { g0[k] = -BIG; g1[k] = -BIG; g2[k] = -BIG; }
#pragma unroll
            for (int j = 0; j < 3; j++) {
                if (km[0 * 3 + j]) {
#pragma unroll
                    for (int k = 0; k < 4; k++) g0[k] = fmaxf(g0[k], eA[k + j]);
                }
                if (km[1 * 3 + j]) {
#pragma unroll
                    for (int k = 0; k < 4; k++) g1[k] = fmaxf(g1[k], eA[k + j]);
                }
                if (km[2 * 3 + j]) {
#pragma unroll
                    for (int k = 0; k < 4; k++) g2[k] = fmaxf(g2[k], eA[k + j]);
                }
            }
#pragma unroll
            for (int k = 0; k < 4; k++) {
                dC[k] = g0[k];
                dB[k] = fmaxf(dB[k], g1[k]);
                dA[k] = fmaxf(dA[k], g2[k]);
            }
        }

        // ---- dA now complete: output row sy = q-2 ----
        if (q >= y0 + 2) {
            int sy = q - 2;
            *reinterpret_cast<float4*>(dst + sy * IMW + x0) =
                make_float4(dA[0], dA[1], dA[2], dA[3]);
        }

        // ---- rotate pipelines ----
#pragma unroll
        for (int k = 0; k < 6; k++) { eA[k] = eB[k]; eB[k] = eC[k]; }
#pragma unroll
        for (int k = 0; k < 4; k++) { dA[k] = dB[k]; dB[k] = dC[k]; }
    }
}

__global__ __launch_bounds__(NTHREADS)
void opening_kernel(const float* __restrict__ img,
                    const int*   __restrict__ ker,
                    float*       __restrict__ out)
{
    int km[9];
#pragma unroll
    for (int i = 0; i < 9; i++) km[i] = ker[i];
    const bool cross = (km[0] == 0) && (km[1] == 1) && (km[2] == 0) &&
                       (km[3] == 1) && (km[4] == 1) && (km[5] == 1) &&
                       (km[6] == 0) && (km[7] == 1) && (km[8] == 0);

    const int gw   = blockIdx.x * (NTHREADS / 32) + (threadIdx.x >> 5);
    const int lane = threadIdx.x & 31;
    const int xseg   = gw & (NSEG - 1);
    const int t      = gw >> 3;               // log2(NSEG)=3
    const int ystrip = t & (NSTRIP - 1);
    const int bc     = t >> 5;                // log2(NSTRIP)=5

    const int x0 = xseg * 128 + lane * 4;
    const int y0 = ystrip * TY;

    const float* src = img + (size_t)bc * (IMH * IMW);
    float*       dst = out + (size_t)bc * (IMH * IMW);

    if (cross) run_warp<true >(src, dst, km, x0, y0);
    else       run_warp<false>(src, dst, km, x0, y0);
}

extern "C" void kernel_launch(void* const* d_in, const int* in_sizes, int n_in,
                              void* d_out, int out_size)
{
    const float* img = (const float*)d_in[0];   // [8,3,1024,1024] fp32
    const int*   ker = (const int*)d_in[1];     // [3,3] int32 mask
    float*       out = (float*)d_out;

    const int BC = in_sizes[0] / (IMH * IMW);   // 24
    const int warps  = BC * NSTRIP * NSEG;      // 6144
    const int blocks = warps / (NTHREADS / 32); // 768
    opening_kernel<<<blocks, NTHREADS>>>(img, ker, out);
}

// round 5
// speedup vs baseline: 1.4596x; 1.0360x over previous
#include <cuda_runtime.h>
#include <cuda_bf16.h>

#define BIG 1e4f
#define IMH 1024
#define IMW 1024

constexpr int TY     = 64;                // output rows per warp
constexpr int NSEG   = 8;                 // 1024/128 horizontal warp segments
constexpr int NSTRIP = IMH / TY;          // 16
constexpr int NTHREADS = 256;             // 8 warps / block
// total warps = 24*16*8 = 3072 -> 384 blocks, single resident wave

template<bool CROSS>
__device__ __forceinline__ void run_warp(const float* __restrict__ src,
                                         float*       __restrict__ dst,
                                         const int* km, int x0, int y0)
{
    float eA[6], eB[6];   // erosion accumulators: rows q-1, q
    float dA[4], dB[4];   // dilation accumulators: rows q-2, q-1
#pragma unroll
    for (int k = 0; k < 6; k++) { eA[k] = BIG; eB[k] = BIG; }
#pragma unroll
    for (int k = 0; k < 4; k++) { dA[k] = -BIG; dB[k] = -BIG; }

    const bool xlo = (x0 == 0);              // eroded pos x0-1 == -1
    const bool xhi = (x0 == IMW - 4);        // eroded pos x0+4 == IMW
    // halo pointers: clamp to a safe in-bounds offset, fix up with selects
    const int offL = (x0 >= 2)        ? -2 : 0;
    const int offR = (x0 <= IMW - 8)  ?  4 : 0;
    const bool padL = (x0 < 2);
    const bool padR = (x0 > IMW - 8);
    const float* __restrict__ pbase = src + x0;

#pragma unroll 4
    for (int q = y0 - 2; q <= y0 + TY + 1; q++) {
        // ---- unconditional loads from clamped row, then select-pad ----
        int qc = q < 0 ? 0 : (q >= IMH ? IMH - 1 : q);
        const float* p = pbase + (size_t)qc * IMW;
        float4 v  = *reinterpret_cast<const float4*>(p);
        float2 lv = *reinterpret_cast<const float2*>(p + offL);
        float2 rv = *reinterpret_cast<const float2*>(p + offR);
        if (padL) { lv.x = BIG; lv.y = BIG; }
        if (padR) { rv.x = BIG; rv.y = BIG; }
        float w[8];
        w[0]=lv.x; w[1]=lv.y; w[2]=v.x; w[3]=v.y; w[4]=v.z; w[5]=v.w; w[6]=rv.x; w[7]=rv.y;
        if (q < 0 || q >= IMH) {
#pragma unroll
            for (int k = 0; k < 8; k++) w[k] = BIG;
        }

        // ---- erosion contributions of input row q (6-wide: x0-1..x0+4) ----
        float eC[6];
        if (CROSS) {
#pragma unroll
            for (int k = 0; k < 6; k++) {
                float h = fminf(fminf(w[k], w[k + 1]), w[k + 2]);
                eC[k] = w[k + 1];               // mask row 0: center only
                eB[k] = fminf(eB[k], h);        // mask row 1: full
                eA[k] = fminf(eA[k], w[k + 1]); // mask row 2: center only
            }
        } else {
            float c0[6], c1[6], c2[6];
#pragma unroll
            for (int k = 0; k < 6; k++) { c0[k] = BIG; c1[k] = BIG; c2[k] = BIG; }
#pragma unroll
            for (int j = 0; j < 3; j++) {
                if (km[0*3 + j]) {
#pragma unroll
                    for (int k = 0; k < 6; k++) c0[k] = fminf(c0[k], w[k + j]);
                }
                if (km[1*3 + j]) {
#pragma unroll
                    for (int k = 0; k < 6; k++) c1[k] = fminf(c1[k], w[k + j]);
                }
                if (km[2*3 + j]) {
#pragma unroll
                    for (int k = 0; k < 6; k++) c2[k] = fminf(c2[k], w[k + j]);
                }
            }
#pragma unroll
            for (int k = 0; k < 6; k++) {
                eC[k] = c0[k];
                eB[k] = fminf(eB[k], c1[k]);
                eA[k] = fminf(eA[k], c2[k]);
            }
        }

        // ---- eA complete: eroded row ry = q-1; apply -BIG padding ----
        int ry = q - 1;
        if (ry < 0 || ry >= IMH) {
#pragma unroll
            for (int k = 0; k < 6; k++) eA[k] = -BIG;
        } else {
            if (xlo) eA[0] = -BIG;
            if (xhi) eA[5] = -BIG;
        }

        // ---- dilation contributions of eroded row ry (4-wide) ----
        float dC[4];
        if (CROSS) {
#pragma unroll
            for (int k = 0; k < 4; k++) {
                float g = fmaxf(fmaxf(eA[k], eA[k + 1]), eA[k + 2]);
                dC[k] = eA[k + 1];
                dB[k] = fmaxf(dB[k], g);
                dA[k] = fmaxf(dA[k], eA[k + 1]);
            }
        } else {
            float g0[4], g1[4], g2[4];
#pragma unroll
            for (int k = 0; k < 4; k++) { g0[k] = -BIG; g1[k] = -BIG; g2[k] = -BIG; }
#pragma unroll
            for (int j = 0; j < 3; j++) {
                if (km[0*3 + j]) {
#pragma unroll
                    for (int k = 0; k < 4; k++) g0[k] = fmaxf(g0[k], eA[k + j]);
                }
                if (km[1*3 + j]) {
#pragma unroll
                    for (int k = 0; k < 4; k++) g1[k] = fmaxf(g1[k], eA[k + j]);
                }
                if (km[2*3 + j]) {
#pragma unroll
                    for (int k = 0; k < 4; k++) g2[k] = fmaxf(g2[k], eA[k + j]);
                }
            }
#pragma unroll
            for (int k = 0; k < 4; k++) {
                dC[k] = g0[k];
                dB[k] = fmaxf(dB[k], g1[k]);
                dA[k] = fmaxf(dA[k], g2[k]);
            }
        }

        // ---- dA complete: output row sy = q-2 ----
        if (q >= y0 + 2) {
            int sy = q - 2;
            *reinterpret_cast<float4*>(dst + (size_t)sy * IMW + x0) =
                make_float4(dA[0], dA[1], dA[2], dA[3]);
        }

        // ---- rotate pipelines ----
#pragma unroll
        for (int k = 0; k < 6; k++) { eA[k] = eB[k]; eB[k] = eC[k]; }
#pragma unroll
        for (int k = 0; k < 4; k++) { dA[k] = dB[k]; dB[k] = dC[k]; }
    }
}

__global__ __launch_bounds__(NTHREADS)
void opening_kernel(const float* __restrict__ img,
                    const int*   __restrict__ ker,
                    float*       __restrict__ out)
{
    int km[9];
#pragma unroll
    for (int i = 0; i < 9; i++) km[i] = ker[i];
    const bool cross = (km[0] == 0) && (km[1] == 1) && (km[2] == 0) &&
                       (km[3] == 1) && (km[4] == 1) && (km[5] == 1) &&
                       (km[6] == 0) && (km[7] == 1) && (km[8] == 0);

    const int gw   = blockIdx.x * (NTHREADS / 32) + (threadIdx.x >> 5);
    const int lane = threadIdx.x & 31;
    const int xseg   = gw & (NSEG - 1);
    const int t      = gw >> 3;               // log2(NSEG)=3
    const int ystrip = t & (NSTRIP - 1);
    const int bc     = t >> 4;                // log2(NSTRIP)=4

    const int x0 = xseg * 128 + lane * 4;
    const int y0 = ystrip * TY;

    const float* src = img + (size_t)bc * (IMH * IMW);
    float*       dst = out + (size_t)bc * (IMH * IMW);

    if (cross) run_warp<true >(src, dst, km, x0, y0);
    else       run_warp<false>(src, dst, km, x0, y0);
}

extern "C" void kernel_launch(void* const* d_in, const int* in_sizes, int n_in,
                              void* d_out, int out_size)
{
    const float* img = (const float*)d_in[0];   // [8,3,1024,1024] fp32
    const int*   ker = (const int*)d_in[1];     // [3,3] int32 mask
    float*       out = (float*)d_out;

    const int BC = in_sizes[0] / (IMH * IMW);   // 24
    const int warps  = BC * NSTRIP * NSEG;      // 3072
    const int blocks = warps / (NTHREADS / 32); // 384
    opening_kernel<<<blocks, NTHREADS>>>(img, ker, out);
}